// round 8
// baseline (speedup 1.0000x reference)
#include <cuda_runtime.h>
#include <cuda_bf16.h>
#include <cstdint>

#define N_NODES 16384
#define N_EDGES 65536

// Scratch for layer-1 output (h1), 16384 x 64 f32 = 4 MB.
__device__ float g_h1[N_NODES * 64];

// ---------- packed f32x2 helpers (Blackwell FFMA2; relu via 2x FMNMX) ----------
__device__ __forceinline__ unsigned long long ffma2(unsigned long long a,
                                                    unsigned long long b,
                                                    unsigned long long c) {
    unsigned long long d;
    asm("fma.rn.f32x2 %0, %1, %2, %3;" : "=l"(d) : "l"(a), "l"(b), "l"(c));
    return d;
}
__device__ __forceinline__ unsigned long long pack2(float x, float y) {
    unsigned long long r;
    asm("mov.b64 %0, {%1, %2};" : "=l"(r) : "f"(x), "f"(y));
    return r;
}
__device__ __forceinline__ float2 unpack2(unsigned long long v) {
    float2 f;
    asm("mov.b64 {%0, %1}, %2;" : "=f"(f.x), "=f"(f.y) : "l"(v));
    return f;
}
__device__ __forceinline__ unsigned long long relu2(unsigned long long v) {
    float2 f = unpack2(v);
    f.x = fmaxf(f.x, 0.f);
    f.y = fmaxf(f.y, 0.f);
    return pack2(f.x, f.y);
}

// ---------------------------------------------------------------------------
// k_init1: h1[n,:] = x[n,:8] @ root1[8,64] + bias1. One warp per node.
// ---------------------------------------------------------------------------
__global__ void k_init1(const float* __restrict__ x,
                        const float* __restrict__ root1,
                        const float* __restrict__ bias1) {
    __shared__ float sroot[512];
    __shared__ float sbias[64];
    int t = threadIdx.x;
    for (int k = t; k < 512; k += 256) sroot[k] = root1[k];
    if (t < 64) sbias[t] = bias1[t];
    __syncthreads();

    int warp = t >> 5, lane = t & 31;
    int n = blockIdx.x * 8 + warp;
    float acc0 = sbias[lane], acc1 = sbias[lane + 32];
    const float* xr = x + n * 8;
#pragma unroll
    for (int i = 0; i < 8; i++) {
        float xv = __ldg(xr + i);
        acc0 = fmaf(xv, sroot[i * 64 + lane], acc0);
        acc1 = fmaf(xv, sroot[i * 64 + lane + 32], acc1);
    }
    g_h1[n * 64 + lane] = acc0;
    g_h1[n * 64 + lane + 32] = acc1;
}

// ---------------------------------------------------------------------------
// k_edge1: layer-1 edge messages (c_in=8 -> 4 i-pairs), packed f32x2,
// 8 edges per warp-iteration, atomically scattered into h1.
// edge_index is int32 (JAX x64 disabled).
// ---------------------------------------------------------------------------
#define EPB1 8
__global__ void __launch_bounds__(256, 2)
k_edge1(const float* __restrict__ x,
        const int* __restrict__ ei,
        const float* __restrict__ ea,
        const float* __restrict__ A1,
        const float* __restrict__ b1) {
    __shared__ float4 sWlo[4 * 32];   // [p][o] {P0,P1,Q0,Q1} for cols o
    __shared__ float4 sWhi[4 * 32];   // same for o+32
    __shared__ float4 sB[4 * 32];     // {Blo0,Blo1,Bhi0,Bhi1}
    __shared__ float  sx[8][EPB1 * 8];  // per warp: 8 edges x 8 feats

    int t = threadIdx.x;
    for (int k = t; k < 128; k += 256) {
        int p = k >> 5, o = k & 31;
        int i0 = 2 * p;
        sWlo[k] = make_float4(A1[i0 * 64 + o],       A1[(i0 + 1) * 64 + o],
                              A1[512 + i0 * 64 + o], A1[512 + (i0 + 1) * 64 + o]);
        sWhi[k] = make_float4(A1[i0 * 64 + o + 32],       A1[(i0 + 1) * 64 + o + 32],
                              A1[512 + i0 * 64 + o + 32], A1[512 + (i0 + 1) * 64 + o + 32]);
        sB[k]   = make_float4(b1[i0 * 64 + o],      b1[(i0 + 1) * 64 + o],
                              b1[i0 * 64 + o + 32], b1[(i0 + 1) * 64 + o + 32]);
    }
    __syncthreads();

    int warp = t >> 5, lane = t & 31;
    const unsigned long long* sx2 = (const unsigned long long*)sx[warp];
    const ulonglong2* pWlo = (const ulonglong2*)sWlo;
    const ulonglong2* pWhi = (const ulonglong2*)sWhi;
    const ulonglong2* pB   = (const ulonglong2*)sB;

    int gw = blockIdx.x * 8 + warp;
    int nwarps = gridDim.x * 8;
    const int* src = ei;
    const int* dst = ei + N_EDGES;

    for (int g = gw; g < N_EDGES / EPB1; g += nwarps) {
        int e0 = g * EPB1;
        {   // stage x rows: lane -> (edge = lane>>2, float2 j = lane&3)
            int e = lane >> 2, j = lane & 3;
            int s = src[e0 + e];
            float2 v = *(const float2*)(x + (size_t)s * 8 + j * 2);
            ((float2*)sx[warp])[e * 4 + j] = v;
        }
        unsigned long long a0d[EPB1], a1d[EPB1];
#pragma unroll
        for (int e = 0; e < EPB1; e++) {
            float2 at = *(const float2*)(ea + (size_t)(e0 + e) * 2);
            a0d[e] = pack2(at.x, at.x);
            a1d[e] = pack2(at.y, at.y);
        }
        __syncwarp();

        unsigned long long accL[EPB1], accH[EPB1];
#pragma unroll
        for (int e = 0; e < EPB1; e++) { accL[e] = 0ull; accH[e] = 0ull; }
#pragma unroll
        for (int p = 0; p < 4; p++) {
            ulonglong2 wlo = pWlo[p * 32 + lane];
            ulonglong2 whi = pWhi[p * 32 + lane];
            ulonglong2 bb  = pB[p * 32 + lane];     // .x={Blo0,Blo1} .y={Bhi0,Bhi1}
#pragma unroll
            for (int e = 0; e < EPB1; e++) {
                unsigned long long h2 = sx2[e * 4 + p];
                unsigned long long wl = ffma2(a0d[e], wlo.x, bb.x);
                wl = relu2(ffma2(a1d[e], wlo.y, wl));
                accL[e] = ffma2(h2, wl, accL[e]);
                unsigned long long wh = ffma2(a0d[e], whi.x, bb.y);
                wh = relu2(ffma2(a1d[e], whi.y, wh));
                accH[e] = ffma2(h2, wh, accH[e]);
            }
        }
#pragma unroll
        for (int e = 0; e < EPB1; e++) {
            int d = dst[e0 + e];
            float2 al = unpack2(accL[e]);
            float2 ah = unpack2(accH[e]);
            atomicAdd(&g_h1[d * 64 + lane],      al.x + al.y);
            atomicAdd(&g_h1[d * 64 + lane + 32], ah.x + ah.y);
        }
        __syncwarp();
    }
}

// ---------------------------------------------------------------------------
// k_init2: out[n,:] = h1[n,:64] @ root2[64,64] + bias2. 4 nodes per warp.
// ---------------------------------------------------------------------------
__global__ void k_init2(const float* __restrict__ root2,
                        const float* __restrict__ bias2,
                        float* __restrict__ out) {
    __shared__ float2 sR[64 * 32];
    __shared__ float  sb[64];
    int t = threadIdx.x;
    for (int k = t; k < 2048; k += 256) {
        int i = k >> 5, o = k & 31;
        sR[k] = make_float2(root2[i * 64 + o], root2[i * 64 + o + 32]);
    }
    if (t < 64) sb[t] = bias2[t];
    __syncthreads();

    int warp = t >> 5, lane = t & 31;
    int n0 = (blockIdx.x * 8 + warp) * 4;
    float hlo[4], hhi[4], acc0[4], acc1[4];
#pragma unroll
    for (int n = 0; n < 4; n++) {
        hlo[n] = g_h1[(n0 + n) * 64 + lane];
        hhi[n] = g_h1[(n0 + n) * 64 + lane + 32];
        acc0[n] = sb[lane];
        acc1[n] = sb[lane + 32];
    }
#pragma unroll
    for (int i = 0; i < 64; i++) {
        float2 r = sR[i * 32 + lane];
#pragma unroll
        for (int n = 0; n < 4; n++) {
            float hv = __shfl_sync(0xffffffffu, (i < 32) ? hlo[n] : hhi[n], i & 31);
            acc0[n] = fmaf(hv, r.x, acc0[n]);
            acc1[n] = fmaf(hv, r.y, acc1[n]);
        }
    }
#pragma unroll
    for (int n = 0; n < 4; n++) {
        out[(n0 + n) * 64 + lane]      = acc0[n];
        out[(n0 + n) * 64 + lane + 32] = acc1[n];
    }
}

// ---------------------------------------------------------------------------
// k_edge2: hot kernel. Packed-over-i f32x2, 8 edges/warp-iter (best instr mix,
// ~364 issues/edge), now capped at 85 regs via __launch_bounds__(256,3) to get
// 3 blocks/SM (6 warps/SMSP) instead of 2 — the R3/R4 comparison showed the
// kernel is issue-bound and occupancy, not instr count, is the current lever.
//   msg[e,o] = sum_i h1[src[e],i] * relu(a0*P[i,o] + a1*Q[i,o] + B[i,o])
// smem: sWlo 16K | sWhi 16K | sB 16K | staging 16K = 65536 B (x3 = 192K/SM).
// ---------------------------------------------------------------------------
#define EPB2 8
__global__ void __launch_bounds__(256, 3)
k_edge2(const int* __restrict__ ei,
        const float* __restrict__ ea,
        const float* __restrict__ A2,
        const float* __restrict__ b2,
        float* __restrict__ out) {
    extern __shared__ float smem[];
    float4* sWlo = (float4*)smem;                       // [32p][32o] {P0,P1,Q0,Q1}
    float4* sWhi = (float4*)(smem + 4096);              // same for o+32
    float4* sB   = (float4*)(smem + 8192);              // {Blo0,Blo1,Bhi0,Bhi1}
    float*  sh   = smem + 12288;                        // 8 warps * 8 edges * 64

    int t = threadIdx.x;
    for (int k = t; k < 1024; k += 256) {
        int p = k >> 5, o = k & 31;
        int i0 = 2 * p;
        sWlo[k] = make_float4(A2[i0 * 64 + o],        A2[(i0 + 1) * 64 + o],
                              A2[4096 + i0 * 64 + o], A2[4096 + (i0 + 1) * 64 + o]);
        sWhi[k] = make_float4(A2[i0 * 64 + o + 32],        A2[(i0 + 1) * 64 + o + 32],
                              A2[4096 + i0 * 64 + o + 32], A2[4096 + (i0 + 1) * 64 + o + 32]);
        sB[k]   = make_float4(b2[i0 * 64 + o],      b2[(i0 + 1) * 64 + o],
                              b2[i0 * 64 + o + 32], b2[(i0 + 1) * 64 + o + 32]);
    }
    __syncthreads();

    int warp = t >> 5, lane = t & 31;
    float* shw = sh + warp * (EPB2 * 64);
    const unsigned long long* shw2 = (const unsigned long long*)shw;
    const ulonglong2* pWlo = (const ulonglong2*)sWlo;
    const ulonglong2* pWhi = (const ulonglong2*)sWhi;
    const ulonglong2* pB   = (const ulonglong2*)sB;

    int gw = blockIdx.x * 8 + warp;
    int nwarps = gridDim.x * 8;
    const int* src = ei;
    const int* dst = ei + N_EDGES;

    for (int g = gw; g < N_EDGES / EPB2; g += nwarps) {
        int e0 = g * EPB2;
        unsigned long long a0d[EPB2], a1d[EPB2];
#pragma unroll
        for (int e = 0; e < EPB2; e++) {
            int s = src[e0 + e];
            // gather h1 row (256B coalesced) into smem, pairs over i
            float2 hv = *(const float2*)(&g_h1[s * 64 + lane * 2]);
            ((float2*)shw)[e * 32 + lane] = hv;
            float2 at = *(const float2*)(ea + (size_t)(e0 + e) * 2);
            a0d[e] = pack2(at.x, at.x);
            a1d[e] = pack2(at.y, at.y);
        }
        __syncwarp();

        unsigned long long accL[EPB2], accH[EPB2];
#pragma unroll
        for (int e = 0; e < EPB2; e++) { accL[e] = 0ull; accH[e] = 0ull; }
#pragma unroll 4
        for (int p = 0; p < 32; p++) {
            ulonglong2 wlo = pWlo[p * 32 + lane];   // .x = {P0,P1}, .y = {Q0,Q1}
            ulonglong2 whi = pWhi[p * 32 + lane];
            ulonglong2 bb  = pB[p * 32 + lane];     // .x={Blo0,Blo1} .y={Bhi0,Bhi1}
#pragma unroll
            for (int e = 0; e < EPB2; e++) {
                unsigned long long h2 = shw2[e * 32 + p];   // broadcast
                unsigned long long wl = ffma2(a0d[e], wlo.x, bb.x);
                wl = relu2(ffma2(a1d[e], wlo.y, wl));
                accL[e] = ffma2(h2, wl, accL[e]);
                unsigned long long wh = ffma2(a0d[e], whi.x, bb.y);
                wh = relu2(ffma2(a1d[e], whi.y, wh));
                accH[e] = ffma2(h2, wh, accH[e]);
            }
        }
#pragma unroll
        for (int e = 0; e < EPB2; e++) {
            int d = dst[e0 + e];
            float2 al = unpack2(accL[e]);
            float2 ah = unpack2(accH[e]);
            atomicAdd(&out[d * 64 + lane],      al.x + al.y);
            atomicAdd(&out[d * 64 + lane + 32], ah.x + ah.y);
        }
        __syncwarp();
    }
}

// ---------------------------------------------------------------------------
// Launch: init1 -> edge1 -> init2 -> edge2 (default stream, graph-capturable).
// Inputs (metadata order):
//   0 x[16384,8] f32 | 1 edge_index[2,65536] i32 | 2 edge_attr[65536,2] f32
//   3 A1[2,512] | 4 b1[512] | 5 A2[2,4096] | 6 b2[4096]
//   7 root1[8,64] | 8 bias1[64] | 9 root2[64,64] | 10 bias2[64]
// ---------------------------------------------------------------------------
extern "C" void kernel_launch(void* const* d_in, const int* in_sizes, int n_in,
                              void* d_out, int out_size) {
    const float* x     = (const float*)d_in[0];
    const int*   ei    = (const int*)d_in[1];
    const float* ea    = (const float*)d_in[2];
    const float* A1    = (const float*)d_in[3];
    const float* b1    = (const float*)d_in[4];
    const float* A2    = (const float*)d_in[5];
    const float* b2    = (const float*)d_in[6];
    const float* root1 = (const float*)d_in[7];
    const float* bias1 = (const float*)d_in[8];
    const float* root2 = (const float*)d_in[9];
    const float* bias2 = (const float*)d_in[10];
    float* out = (float*)d_out;

    const int smem2 = 65536;  // 48K weights + 16K staging; x3 blocks = 192K/SM
    cudaFuncSetAttribute(k_edge2, cudaFuncAttributeMaxDynamicSharedMemorySize, smem2);

    k_init1<<<N_NODES / 8, 256>>>(x, root1, bias1);
    k_edge1<<<296, 256>>>(x, ei, ea, A1, b1);
    k_init2<<<N_NODES / 32, 256>>>(root2, bias2, out);
    k_edge2<<<444, 256, smem2>>>(ei, ea, A2, b2, out);
}

// round 9
// speedup vs baseline: 1.0808x; 1.0808x over previous
#include <cuda_runtime.h>
#include <cuda_bf16.h>
#include <cstdint>

#define N_NODES 16384
#define N_EDGES 65536

// Scratch for layer-1 output (h1), 16384 x 64 f32 = 4 MB.
__device__ float g_h1[N_NODES * 64];

// ---------- packed f32x2 helpers (Blackwell FFMA2; relu via 2x FMNMX) ----------
__device__ __forceinline__ unsigned long long ffma2(unsigned long long a,
                                                    unsigned long long b,
                                                    unsigned long long c) {
    unsigned long long d;
    asm("fma.rn.f32x2 %0, %1, %2, %3;" : "=l"(d) : "l"(a), "l"(b), "l"(c));
    return d;
}
__device__ __forceinline__ unsigned long long pack2(float x, float y) {
    unsigned long long r;
    asm("mov.b64 %0, {%1, %2};" : "=l"(r) : "f"(x), "f"(y));
    return r;
}
__device__ __forceinline__ float2 unpack2(unsigned long long v) {
    float2 f;
    asm("mov.b64 {%0, %1}, %2;" : "=f"(f.x), "=f"(f.y) : "l"(v));
    return f;
}
__device__ __forceinline__ unsigned long long relu2(unsigned long long v) {
    float2 f = unpack2(v);
    f.x = fmaxf(f.x, 0.f);
    f.y = fmaxf(f.y, 0.f);
    return pack2(f.x, f.y);
}

// ---------------------------------------------------------------------------
// k_init1: h1[n,:] = x[n,:8] @ root1[8,64] + bias1. One warp per node.
// ---------------------------------------------------------------------------
__global__ void k_init1(const float* __restrict__ x,
                        const float* __restrict__ root1,
                        const float* __restrict__ bias1) {
    __shared__ float sroot[512];
    __shared__ float sbias[64];
    int t = threadIdx.x;
    for (int k = t; k < 512; k += 256) sroot[k] = root1[k];
    if (t < 64) sbias[t] = bias1[t];
    __syncthreads();

    int warp = t >> 5, lane = t & 31;
    int n = blockIdx.x * 8 + warp;
    float acc0 = sbias[lane], acc1 = sbias[lane + 32];
    const float* xr = x + n * 8;
#pragma unroll
    for (int i = 0; i < 8; i++) {
        float xv = __ldg(xr + i);
        acc0 = fmaf(xv, sroot[i * 64 + lane], acc0);
        acc1 = fmaf(xv, sroot[i * 64 + lane + 32], acc1);
    }
    g_h1[n * 64 + lane] = acc0;
    g_h1[n * 64 + lane + 32] = acc1;
}

// ---------------------------------------------------------------------------
// k_edge1: layer-1 edge messages (c_in=8 -> 4 i-pairs), packed f32x2,
// 8 edges per warp-iteration, atomically scattered into h1.
// edge_index is int32 (JAX x64 disabled).
// ---------------------------------------------------------------------------
#define EPB1 8
__global__ void __launch_bounds__(256, 2)
k_edge1(const float* __restrict__ x,
        const int* __restrict__ ei,
        const float* __restrict__ ea,
        const float* __restrict__ A1,
        const float* __restrict__ b1) {
    __shared__ float4 sWlo[4 * 32];   // [p][o] {P0,P1,Q0,Q1} for cols o
    __shared__ float4 sWhi[4 * 32];   // same for o+32
    __shared__ float4 sB[4 * 32];     // {Blo0,Blo1,Bhi0,Bhi1}
    __shared__ float  sx[8][EPB1 * 8];  // per warp: 8 edges x 8 feats

    int t = threadIdx.x;
    for (int k = t; k < 128; k += 256) {
        int p = k >> 5, o = k & 31;
        int i0 = 2 * p;
        sWlo[k] = make_float4(A1[i0 * 64 + o],       A1[(i0 + 1) * 64 + o],
                              A1[512 + i0 * 64 + o], A1[512 + (i0 + 1) * 64 + o]);
        sWhi[k] = make_float4(A1[i0 * 64 + o + 32],       A1[(i0 + 1) * 64 + o + 32],
                              A1[512 + i0 * 64 + o + 32], A1[512 + (i0 + 1) * 64 + o + 32]);
        sB[k]   = make_float4(b1[i0 * 64 + o],      b1[(i0 + 1) * 64 + o],
                              b1[i0 * 64 + o + 32], b1[(i0 + 1) * 64 + o + 32]);
    }
    __syncthreads();

    int warp = t >> 5, lane = t & 31;
    const unsigned long long* sx2 = (const unsigned long long*)sx[warp];
    const ulonglong2* pWlo = (const ulonglong2*)sWlo;
    const ulonglong2* pWhi = (const ulonglong2*)sWhi;
    const ulonglong2* pB   = (const ulonglong2*)sB;

    int gw = blockIdx.x * 8 + warp;
    int nwarps = gridDim.x * 8;
    const int* src = ei;
    const int* dst = ei + N_EDGES;

    for (int g = gw; g < N_EDGES / EPB1; g += nwarps) {
        int e0 = g * EPB1;
        {   // stage x rows: lane -> (edge = lane>>2, float2 j = lane&3)
            int e = lane >> 2, j = lane & 3;
            int s = src[e0 + e];
            float2 v = *(const float2*)(x + (size_t)s * 8 + j * 2);
            ((float2*)sx[warp])[e * 4 + j] = v;
        }
        unsigned long long a0d[EPB1], a1d[EPB1];
#pragma unroll
        for (int e = 0; e < EPB1; e++) {
            float2 at = *(const float2*)(ea + (size_t)(e0 + e) * 2);
            a0d[e] = pack2(at.x, at.x);
            a1d[e] = pack2(at.y, at.y);
        }
        __syncwarp();

        unsigned long long accL[EPB1], accH[EPB1];
#pragma unroll
        for (int e = 0; e < EPB1; e++) { accL[e] = 0ull; accH[e] = 0ull; }
#pragma unroll
        for (int p = 0; p < 4; p++) {
            ulonglong2 wlo = pWlo[p * 32 + lane];
            ulonglong2 whi = pWhi[p * 32 + lane];
            ulonglong2 bb  = pB[p * 32 + lane];     // .x={Blo0,Blo1} .y={Bhi0,Bhi1}
#pragma unroll
            for (int e = 0; e < EPB1; e++) {
                unsigned long long h2 = sx2[e * 4 + p];
                unsigned long long wl = ffma2(a0d[e], wlo.x, bb.x);
                wl = relu2(ffma2(a1d[e], wlo.y, wl));
                accL[e] = ffma2(h2, wl, accL[e]);
                unsigned long long wh = ffma2(a0d[e], whi.x, bb.y);
                wh = relu2(ffma2(a1d[e], whi.y, wh));
                accH[e] = ffma2(h2, wh, accH[e]);
            }
        }
#pragma unroll
        for (int e = 0; e < EPB1; e++) {
            int d = dst[e0 + e];
            float2 al = unpack2(accL[e]);
            float2 ah = unpack2(accH[e]);
            atomicAdd(&g_h1[d * 64 + lane],      al.x + al.y);
            atomicAdd(&g_h1[d * 64 + lane + 32], ah.x + ah.y);
        }
        __syncwarp();
    }
}

// ---------------------------------------------------------------------------
// k_init2: out[n,:] = h1[n,:64] @ root2[64,64] + bias2. 4 nodes per warp.
// ---------------------------------------------------------------------------
__global__ void k_init2(const float* __restrict__ root2,
                        const float* __restrict__ bias2,
                        float* __restrict__ out) {
    __shared__ float2 sR[64 * 32];
    __shared__ float  sb[64];
    int t = threadIdx.x;
    for (int k = t; k < 2048; k += 256) {
        int i = k >> 5, o = k & 31;
        sR[k] = make_float2(root2[i * 64 + o], root2[i * 64 + o + 32]);
    }
    if (t < 64) sb[t] = bias2[t];
    __syncthreads();

    int warp = t >> 5, lane = t & 31;
    int n0 = (blockIdx.x * 8 + warp) * 4;
    float hlo[4], hhi[4], acc0[4], acc1[4];
#pragma unroll
    for (int n = 0; n < 4; n++) {
        hlo[n] = g_h1[(n0 + n) * 64 + lane];
        hhi[n] = g_h1[(n0 + n) * 64 + lane + 32];
        acc0[n] = sb[lane];
        acc1[n] = sb[lane + 32];
    }
#pragma unroll
    for (int i = 0; i < 64; i++) {
        float2 r = sR[i * 32 + lane];
#pragma unroll
        for (int n = 0; n < 4; n++) {
            float hv = __shfl_sync(0xffffffffu, (i < 32) ? hlo[n] : hhi[n], i & 31);
            acc0[n] = fmaf(hv, r.x, acc0[n]);
            acc1[n] = fmaf(hv, r.y, acc1[n]);
        }
    }
#pragma unroll
    for (int n = 0; n < 4; n++) {
        out[(n0 + n) * 64 + lane]      = acc0[n];
        out[(n0 + n) * 64 + lane + 32] = acc1[n];
    }
}

// ---------------------------------------------------------------------------
// k_edge2: hot kernel, o-SPLIT version. A PAIR of warps co-owns each 8-edge
// group: warp half=0 computes output cols [0,32), half=1 cols [32,64).
// Halves acc registers (16 vs 32) -> ~80 regs -> TRUE 3 blocks/SM, no spill.
// h read as LDS.128 (2 i-pairs per load); pair syncs via named barrier so
// pairs don't convoy.
//   msg[e,o] = sum_i h1[src[e],i] * relu(a0*P[i,o] + a1*Q[i,o] + B[i,o])
// smem: sW 32K | sB2 16K | staging 4 pairs x 2K = 8K -> 57344 B (x3 = 168K/SM)
// ---------------------------------------------------------------------------
#define EPB2 8
__global__ void __launch_bounds__(256, 3)
k_edge2(const int* __restrict__ ei,
        const float* __restrict__ ea,
        const float* __restrict__ A2,
        const float* __restrict__ b2,
        float* __restrict__ out) {
    extern __shared__ float smem[];
    float4* sW  = (float4*)smem;            // [32p][64oc] {P0,P1,Q0,Q1}  32KB
    float4* sB2 = (float4*)(smem + 8192);   // [16q][64oc] {B4q,B4q+1,B4q+2,B4q+3} 16KB
    float*  sh  = smem + 12288;             // 4 pairs x 8 edges x 64 f32  8KB

    int t = threadIdx.x;
    for (int k = t; k < 2048; k += 256) {
        int p = k >> 6, oc = k & 63;
        int i0 = 2 * p;
        sW[k] = make_float4(A2[i0 * 64 + oc],        A2[(i0 + 1) * 64 + oc],
                            A2[4096 + i0 * 64 + oc], A2[4096 + (i0 + 1) * 64 + oc]);
    }
    for (int k = t; k < 1024; k += 256) {
        int q = k >> 6, oc = k & 63;
        sB2[k] = make_float4(b2[(4 * q) * 64 + oc],     b2[(4 * q + 1) * 64 + oc],
                             b2[(4 * q + 2) * 64 + oc], b2[(4 * q + 3) * 64 + oc]);
    }
    __syncthreads();

    int warp = t >> 5, lane = t & 31;
    int pid = warp >> 1, half = warp & 1;
    int oc = half * 32 + lane;
    int barid = 1 + pid;                    // named barrier per warp-pair

    float* shw = sh + pid * 512;            // this pair's 8x64 staging
    const ulonglong2* psh = (const ulonglong2*)shw;
    const ulonglong2* pW  = (const ulonglong2*)sW;
    const ulonglong2* pB2 = (const ulonglong2*)sB2;

    const int* src = ei;
    const int* dst = ei + N_EDGES;
    int gp = blockIdx.x * 4 + pid;          // pair id, grid-wide
    int npairs = gridDim.x * 4;
    const int ngroups = N_EDGES / EPB2;

    for (int g = gp; g < ngroups; g += npairs) {
        int e0 = g * EPB2;
        // gather: this warp stages its 4 edges (half 0 -> e 0..3, half 1 -> e 4..7)
#pragma unroll
        for (int e4 = 0; e4 < 4; e4++) {
            int e = half * 4 + e4;
            int s = src[e0 + e];
            float2 hv = *(const float2*)(&g_h1[(size_t)s * 64 + lane * 2]);
            ((float2*)shw)[e * 32 + lane] = hv;
        }
        // per-edge attr coefficients (duplicated halves), all 8 edges
        unsigned long long a0d[EPB2], a1d[EPB2];
#pragma unroll
        for (int e = 0; e < EPB2; e++) {
            float2 at = *(const float2*)(ea + (size_t)(e0 + e) * 2);
            a0d[e] = pack2(at.x, at.x);
            a1d[e] = pack2(at.y, at.y);
        }
        asm volatile("bar.sync %0, 64;" :: "r"(barid) : "memory");

        unsigned long long acc[EPB2];
#pragma unroll
        for (int e = 0; e < EPB2; e++) acc[e] = 0ull;
        for (int q = 0; q < 16; q++) {      // 2 i-pairs (4 i's) per iteration
            ulonglong2 w0 = pW[(2 * q) * 64 + oc];       // {P,P},{Q,Q} for i=4q,4q+1
            ulonglong2 w1 = pW[(2 * q + 1) * 64 + oc];   // for i=4q+2,4q+3
            ulonglong2 bb = pB2[q * 64 + oc];            // .x={B4q,B4q+1} .y={B4q+2,B4q+3}
#pragma unroll
            for (int e = 0; e < EPB2; e++) {
                ulonglong2 h4 = psh[e * 16 + q];         // {h4q,h4q+1},{h4q+2,h4q+3} bcast
                unsigned long long wl = ffma2(a0d[e], w0.x, bb.x);
                wl = relu2(ffma2(a1d[e], w0.y, wl));
                acc[e] = ffma2(h4.x, wl, acc[e]);
                wl = ffma2(a0d[e], w1.x, bb.y);
                wl = relu2(ffma2(a1d[e], w1.y, wl));
                acc[e] = ffma2(h4.y, wl, acc[e]);
            }
        }
#pragma unroll
        for (int e = 0; e < EPB2; e++) {
            int d = dst[e0 + e];
            float2 a = unpack2(acc[e]);
            atomicAdd(&out[(size_t)d * 64 + oc], a.x + a.y);
        }
        // protect staging before next gather overwrites it
        asm volatile("bar.sync %0, 64;" :: "r"(barid) : "memory");
    }
}

// ---------------------------------------------------------------------------
// Launch: init1 -> edge1 -> init2 -> edge2 (default stream, graph-capturable).
// Inputs (metadata order):
//   0 x[16384,8] f32 | 1 edge_index[2,65536] i32 | 2 edge_attr[65536,2] f32
//   3 A1[2,512] | 4 b1[512] | 5 A2[2,4096] | 6 b2[4096]
//   7 root1[8,64] | 8 bias1[64] | 9 root2[64,64] | 10 bias2[64]
// ---------------------------------------------------------------------------
extern "C" void kernel_launch(void* const* d_in, const int* in_sizes, int n_in,
                              void* d_out, int out_size) {
    const float* x     = (const float*)d_in[0];
    const int*   ei    = (const int*)d_in[1];
    const float* ea    = (const float*)d_in[2];
    const float* A1    = (const float*)d_in[3];
    const float* b1    = (const float*)d_in[4];
    const float* A2    = (const float*)d_in[5];
    const float* b2    = (const float*)d_in[6];
    const float* root1 = (const float*)d_in[7];
    const float* bias1 = (const float*)d_in[8];
    const float* root2 = (const float*)d_in[9];
    const float* bias2 = (const float*)d_in[10];
    float* out = (float*)d_out;

    const int smem2 = 57344;  // 32K sW + 16K sB2 + 8K staging + pad
    cudaFuncSetAttribute(k_edge2, cudaFuncAttributeMaxDynamicSharedMemorySize, smem2);

    k_init1<<<N_NODES / 8, 256>>>(x, root1, bias1);
    k_edge1<<<296, 256>>>(x, ei, ea, A1, b1);
    k_init2<<<N_NODES / 32, 256>>>(root2, bias2, out);
    k_edge2<<<444, 256, smem2>>>(ei, ea, A2, b2, out);
}

// round 10
// speedup vs baseline: 1.1759x; 1.0879x over previous
#include <cuda_runtime.h>
#include <cuda_bf16.h>
#include <cstdint>

#define N_NODES 16384
#define N_EDGES 65536

// Scratch for layer-1 output (h1), 16384 x 64 f32 = 4 MB. Zeroed by memset node.
__device__ float g_h1[N_NODES * 64];

// ---------- packed f32x2 helpers (Blackwell FFMA2; relu via 2x FMNMX) ----------
__device__ __forceinline__ unsigned long long ffma2(unsigned long long a,
                                                    unsigned long long b,
                                                    unsigned long long c) {
    unsigned long long d;
    asm("fma.rn.f32x2 %0, %1, %2, %3;" : "=l"(d) : "l"(a), "l"(b), "l"(c));
    return d;
}
__device__ __forceinline__ unsigned long long pack2(float x, float y) {
    unsigned long long r;
    asm("mov.b64 %0, {%1, %2};" : "=l"(r) : "f"(x), "f"(y));
    return r;
}
__device__ __forceinline__ float2 unpack2(unsigned long long v) {
    float2 f;
    asm("mov.b64 {%0, %1}, %2;" : "=f"(f.x), "=f"(f.y) : "l"(v));
    return f;
}
__device__ __forceinline__ unsigned long long relu2(unsigned long long v) {
    float2 f = unpack2(v);
    f.x = fmaxf(f.x, 0.f);
    f.y = fmaxf(f.y, 0.f);
    return pack2(f.x, f.y);
}

// ---------------------------------------------------------------------------
// k_fused1: init1 + edge1 in one kernel (h1 pre-zeroed by memset).
//   init part : h1[n,:] += x[n,:8] @ root1 + bias1   (atomicAdd, per node)
//   edge part : h1[dst,:] += msg(e)                  (atomicAdd, 8 edges/warp)
// Both are commutative atomics -> no ordering between units.
// Work units: u in [0,8192) = edge groups of 8; u in [8192,10240) = node octets.
// ---------------------------------------------------------------------------
#define EPB1 8
__global__ void __launch_bounds__(256, 2)
k_fused1(const float* __restrict__ x,
         const int* __restrict__ ei,
         const float* __restrict__ ea,
         const float* __restrict__ A1,
         const float* __restrict__ b1,
         const float* __restrict__ root1,
         const float* __restrict__ bias1) {
    __shared__ float4 sWlo[4 * 32];   // [p][o] {P0,P1,Q0,Q1} for cols o
    __shared__ float4 sWhi[4 * 32];   // same for o+32
    __shared__ float4 sB[4 * 32];     // {Blo0,Blo1,Bhi0,Bhi1}
    __shared__ float  sroot[512];
    __shared__ float  sbias[64];
    __shared__ float  sx[8][EPB1 * 8];  // per warp: 8 edges x 8 feats

    int t = threadIdx.x;
    for (int k = t; k < 128; k += 256) {
        int p = k >> 5, o = k & 31;
        int i0 = 2 * p;
        sWlo[k] = make_float4(A1[i0 * 64 + o],       A1[(i0 + 1) * 64 + o],
                              A1[512 + i0 * 64 + o], A1[512 + (i0 + 1) * 64 + o]);
        sWhi[k] = make_float4(A1[i0 * 64 + o + 32],       A1[(i0 + 1) * 64 + o + 32],
                              A1[512 + i0 * 64 + o + 32], A1[512 + (i0 + 1) * 64 + o + 32]);
        sB[k]   = make_float4(b1[i0 * 64 + o],      b1[(i0 + 1) * 64 + o],
                              b1[i0 * 64 + o + 32], b1[(i0 + 1) * 64 + o + 32]);
    }
    for (int k = t; k < 512; k += 256) sroot[k] = root1[k];
    if (t < 64) sbias[t] = bias1[t];
    __syncthreads();

    int warp = t >> 5, lane = t & 31;
    const unsigned long long* sx2 = (const unsigned long long*)sx[warp];
    const ulonglong2* pWlo = (const ulonglong2*)sWlo;
    const ulonglong2* pWhi = (const ulonglong2*)sWhi;
    const ulonglong2* pB   = (const ulonglong2*)sB;

    int gw = blockIdx.x * 8 + warp;
    int nwarps = gridDim.x * 8;
    const int* src = ei;
    const int* dst = ei + N_EDGES;
    const int nEdgeUnits = N_EDGES / EPB1;          // 8192
    const int nUnits = nEdgeUnits + N_NODES / 8;    // + 2048 node octets

    for (int u = gw; u < nUnits; u += nwarps) {
        if (u < nEdgeUnits) {
            int e0 = u * EPB1;
            {   // stage x rows: lane -> (edge = lane>>2, float2 j = lane&3)
                int e = lane >> 2, j = lane & 3;
                int s = src[e0 + e];
                float2 v = *(const float2*)(x + (size_t)s * 8 + j * 2);
                ((float2*)sx[warp])[e * 4 + j] = v;
            }
            unsigned long long a0d[EPB1], a1d[EPB1];
#pragma unroll
            for (int e = 0; e < EPB1; e++) {
                float2 at = *(const float2*)(ea + (size_t)(e0 + e) * 2);
                a0d[e] = pack2(at.x, at.x);
                a1d[e] = pack2(at.y, at.y);
            }
            __syncwarp();

            unsigned long long accL[EPB1], accH[EPB1];
#pragma unroll
            for (int e = 0; e < EPB1; e++) { accL[e] = 0ull; accH[e] = 0ull; }
#pragma unroll
            for (int p = 0; p < 4; p++) {
                ulonglong2 wlo = pWlo[p * 32 + lane];
                ulonglong2 whi = pWhi[p * 32 + lane];
                ulonglong2 bb  = pB[p * 32 + lane];
#pragma unroll
                for (int e = 0; e < EPB1; e++) {
                    unsigned long long h2 = sx2[e * 4 + p];
                    unsigned long long wl = ffma2(a0d[e], wlo.x, bb.x);
                    wl = relu2(ffma2(a1d[e], wlo.y, wl));
                    accL[e] = ffma2(h2, wl, accL[e]);
                    unsigned long long wh = ffma2(a0d[e], whi.x, bb.y);
                    wh = relu2(ffma2(a1d[e], whi.y, wh));
                    accH[e] = ffma2(h2, wh, accH[e]);
                }
            }
#pragma unroll
            for (int e = 0; e < EPB1; e++) {
                int d = dst[e0 + e];
                float2 al = unpack2(accL[e]);
                float2 ah = unpack2(accH[e]);
                atomicAdd(&g_h1[d * 64 + lane],      al.x + al.y);
                atomicAdd(&g_h1[d * 64 + lane + 32], ah.x + ah.y);
            }
            __syncwarp();
        } else {
            // node octet: 8 nodes, root transform + bias, atomicAdd into h1
            int n0 = (u - nEdgeUnits) * 8;
#pragma unroll
            for (int k = 0; k < 8; k++) {
                int n = n0 + k;
                const float* xr = x + (size_t)n * 8;
                float acc0 = sbias[lane], acc1 = sbias[lane + 32];
#pragma unroll
                for (int i = 0; i < 8; i++) {
                    float xv = __ldg(xr + i);
                    acc0 = fmaf(xv, sroot[i * 64 + lane], acc0);
                    acc1 = fmaf(xv, sroot[i * 64 + lane + 32], acc1);
                }
                atomicAdd(&g_h1[n * 64 + lane],      acc0);
                atomicAdd(&g_h1[n * 64 + lane + 32], acc1);
            }
        }
    }
}

// ---------------------------------------------------------------------------
// k_init2: out[n,:] = h1[n,:64] @ root2[64,64] + bias2. 4 nodes per warp.
// ---------------------------------------------------------------------------
__global__ void k_init2(const float* __restrict__ root2,
                        const float* __restrict__ bias2,
                        float* __restrict__ out) {
    __shared__ float2 sR[64 * 32];
    __shared__ float  sb[64];
    int t = threadIdx.x;
    for (int k = t; k < 2048; k += 256) {
        int i = k >> 5, o = k & 31;
        sR[k] = make_float2(root2[i * 64 + o], root2[i * 64 + o + 32]);
    }
    if (t < 64) sb[t] = bias2[t];
    __syncthreads();

    int warp = t >> 5, lane = t & 31;
    int n0 = (blockIdx.x * 8 + warp) * 4;
    float hlo[4], hhi[4], acc0[4], acc1[4];
#pragma unroll
    for (int n = 0; n < 4; n++) {
        hlo[n] = g_h1[(n0 + n) * 64 + lane];
        hhi[n] = g_h1[(n0 + n) * 64 + lane + 32];
        acc0[n] = sb[lane];
        acc1[n] = sb[lane + 32];
    }
#pragma unroll
    for (int i = 0; i < 64; i++) {
        float2 r = sR[i * 32 + lane];
#pragma unroll
        for (int n = 0; n < 4; n++) {
            float hv = __shfl_sync(0xffffffffu, (i < 32) ? hlo[n] : hhi[n], i & 31);
            acc0[n] = fmaf(hv, r.x, acc0[n]);
            acc1[n] = fmaf(hv, r.y, acc1[n]);
        }
    }
#pragma unroll
    for (int n = 0; n < 4; n++) {
        out[(n0 + n) * 64 + lane]      = acc0[n];
        out[(n0 + n) * 64 + lane + 32] = acc1[n];
    }
}

// ---------------------------------------------------------------------------
// k_edge2: hot kernel (R4 core — best measured). Packed-over-i f32x2,
// 8 edges/warp-iter, warp-independent groups. NEW: dst indices prefetched
// as 2x LDG.128 in the gather phase so the epilogue atomics don't eat an
// exposed L2 round-trip.
//   msg[e,o] = sum_i h1[src[e],i] * relu(a0*P[i,o] + a1*Q[i,o] + B[i,o])
// smem: sWlo 16K | sWhi 16K | sB 16K | staging 16K = 65536 B.
// ---------------------------------------------------------------------------
#define EPB2 8
__global__ void __launch_bounds__(256, 2)
k_edge2(const int* __restrict__ ei,
        const float* __restrict__ ea,
        const float* __restrict__ A2,
        const float* __restrict__ b2,
        float* __restrict__ out) {
    extern __shared__ float smem[];
    float4* sWlo = (float4*)smem;                       // [32p][32o] {P0,P1,Q0,Q1}
    float4* sWhi = (float4*)(smem + 4096);              // same for o+32
    float4* sB   = (float4*)(smem + 8192);              // {Blo0,Blo1,Bhi0,Bhi1}
    float*  sh   = smem + 12288;                        // 8 warps * 8 edges * 64

    int t = threadIdx.x;
    for (int k = t; k < 1024; k += 256) {
        int p = k >> 5, o = k & 31;
        int i0 = 2 * p;
        sWlo[k] = make_float4(A2[i0 * 64 + o],        A2[(i0 + 1) * 64 + o],
                              A2[4096 + i0 * 64 + o], A2[4096 + (i0 + 1) * 64 + o]);
        sWhi[k] = make_float4(A2[i0 * 64 + o + 32],        A2[(i0 + 1) * 64 + o + 32],
                              A2[4096 + i0 * 64 + o + 32], A2[4096 + (i0 + 1) * 64 + o + 32]);
        sB[k]   = make_float4(b2[i0 * 64 + o],      b2[(i0 + 1) * 64 + o],
                              b2[i0 * 64 + o + 32], b2[(i0 + 1) * 64 + o + 32]);
    }
    __syncthreads();

    int warp = t >> 5, lane = t & 31;
    float* shw = sh + warp * (EPB2 * 64);
    const unsigned long long* shw2 = (const unsigned long long*)shw;
    const ulonglong2* pWlo = (const ulonglong2*)sWlo;
    const ulonglong2* pWhi = (const ulonglong2*)sWhi;
    const ulonglong2* pB   = (const ulonglong2*)sB;

    int gw = blockIdx.x * 8 + warp;
    int nwarps = gridDim.x * 8;
    const int* src = ei;
    const int* dst = ei + N_EDGES;

    for (int g = gw; g < N_EDGES / EPB2; g += nwarps) {
        int e0 = g * EPB2;
        // prefetch dst indices early (hidden behind the 32-p compute below)
        int4 dA = *(const int4*)(dst + e0);
        int4 dB = *(const int4*)(dst + e0 + 4);
        unsigned long long a0d[EPB2], a1d[EPB2];
#pragma unroll
        for (int e = 0; e < EPB2; e++) {
            int s = src[e0 + e];
            // gather h1 row (256B coalesced) into smem, pairs over i
            float2 hv = *(const float2*)(&g_h1[s * 64 + lane * 2]);
            ((float2*)shw)[e * 32 + lane] = hv;
            float2 at = *(const float2*)(ea + (size_t)(e0 + e) * 2);
            a0d[e] = pack2(at.x, at.x);
            a1d[e] = pack2(at.y, at.y);
        }
        __syncwarp();

        unsigned long long accL[EPB2], accH[EPB2];
#pragma unroll
        for (int e = 0; e < EPB2; e++) { accL[e] = 0ull; accH[e] = 0ull; }
#pragma unroll 4
        for (int p = 0; p < 32; p++) {
            ulonglong2 wlo = pWlo[p * 32 + lane];   // .x = {P0,P1}, .y = {Q0,Q1}
            ulonglong2 whi = pWhi[p * 32 + lane];
            ulonglong2 bb  = pB[p * 32 + lane];     // .x={Blo0,Blo1} .y={Bhi0,Bhi1}
#pragma unroll
            for (int e = 0; e < EPB2; e++) {
                unsigned long long h2 = shw2[e * 32 + p];   // broadcast
                unsigned long long wl = ffma2(a0d[e], wlo.x, bb.x);
                wl = relu2(ffma2(a1d[e], wlo.y, wl));
                accL[e] = ffma2(h2, wl, accL[e]);
                unsigned long long wh = ffma2(a0d[e], whi.x, bb.y);
                wh = relu2(ffma2(a1d[e], whi.y, wh));
                accH[e] = ffma2(h2, wh, accH[e]);
            }
        }
        int dd[EPB2] = {dA.x, dA.y, dA.z, dA.w, dB.x, dB.y, dB.z, dB.w};
#pragma unroll
        for (int e = 0; e < EPB2; e++) {
            float2 al = unpack2(accL[e]);
            float2 ah = unpack2(accH[e]);
            atomicAdd(&out[(size_t)dd[e] * 64 + lane],      al.x + al.y);
            atomicAdd(&out[(size_t)dd[e] * 64 + lane + 32], ah.x + ah.y);
        }
        __syncwarp();
    }
}

// ---------------------------------------------------------------------------
// Launch: memset(h1) -> fused1 -> init2 -> edge2 (graph-capturable: memset
// node + 3 kernel nodes, no allocations).
// Inputs (metadata order):
//   0 x[16384,8] f32 | 1 edge_index[2,65536] i32 | 2 edge_attr[65536,2] f32
//   3 A1[2,512] | 4 b1[512] | 5 A2[2,4096] | 6 b2[4096]
//   7 root1[8,64] | 8 bias1[64] | 9 root2[64,64] | 10 bias2[64]
// ---------------------------------------------------------------------------
extern "C" void kernel_launch(void* const* d_in, const int* in_sizes, int n_in,
                              void* d_out, int out_size) {
    const float* x     = (const float*)d_in[0];
    const int*   ei    = (const int*)d_in[1];
    const float* ea    = (const float*)d_in[2];
    const float* A1    = (const float*)d_in[3];
    const float* b1    = (const float*)d_in[4];
    const float* A2    = (const float*)d_in[5];
    const float* b2    = (const float*)d_in[6];
    const float* root1 = (const float*)d_in[7];
    const float* bias1 = (const float*)d_in[8];
    const float* root2 = (const float*)d_in[9];
    const float* bias2 = (const float*)d_in[10];
    float* out = (float*)d_out;

    void* h1_ptr = nullptr;
    cudaGetSymbolAddress(&h1_ptr, g_h1);

    const int smem2 = 65536;
    cudaFuncSetAttribute(k_edge2, cudaFuncAttributeMaxDynamicSharedMemorySize, smem2);

    cudaMemsetAsync(h1_ptr, 0, (size_t)N_NODES * 64 * sizeof(float));
    k_fused1<<<296, 256>>>(x, ei, ea, A1, b1, root1, bias1);
    k_init2<<<N_NODES / 32, 256>>>(root2, bias2, out);
    k_edge2<<<296, 256, smem2>>>(ei, ea, A2, b2, out);
}

// round 11
// speedup vs baseline: 1.1835x; 1.0065x over previous
#include <cuda_runtime.h>
#include <cuda_bf16.h>
#include <cstdint>

#define N_NODES 16384
#define N_EDGES 65536

// Scratch for layer-1 output (h1), 16384 x 64 f32 = 4 MB.
__device__ float g_h1[N_NODES * 64];

// ---------- packed f32x2 helpers (Blackwell FFMA2; relu via 2x FMNMX) ----------
__device__ __forceinline__ unsigned long long ffma2(unsigned long long a,
                                                    unsigned long long b,
                                                    unsigned long long c) {
    unsigned long long d;
    asm("fma.rn.f32x2 %0, %1, %2, %3;" : "=l"(d) : "l"(a), "l"(b), "l"(c));
    return d;
}
__device__ __forceinline__ unsigned long long pack2(float x, float y) {
    unsigned long long r;
    asm("mov.b64 %0, {%1, %2};" : "=l"(r) : "f"(x), "f"(y));
    return r;
}
__device__ __forceinline__ float2 unpack2(unsigned long long v) {
    float2 f;
    asm("mov.b64 {%0, %1}, %2;" : "=f"(f.x), "=f"(f.y) : "l"(v));
    return f;
}
__device__ __forceinline__ unsigned long long relu2(unsigned long long v) {
    float2 f = unpack2(v);
    f.x = fmaxf(f.x, 0.f);
    f.y = fmaxf(f.y, 0.f);
    return pack2(f.x, f.y);
}
// vector reduction: one REDG for two adjacent f32 columns (FA3 epilogue pattern)
__device__ __forceinline__ void red_v2(float* ptr, float v0, float v1) {
    asm volatile("red.global.v2.f32.add [%0], {%1, %2};"
                 :: "l"(ptr), "f"(v0), "f"(v1) : "memory");
}

// ---------------------------------------------------------------------------
// k_init1: h1[n,:] = x[n,:8] @ root1[8,64] + bias1. One warp per node,
// plain stores (runs before edge1).
// ---------------------------------------------------------------------------
__global__ void k_init1(const float* __restrict__ x,
                        const float* __restrict__ root1,
                        const float* __restrict__ bias1) {
    __shared__ float sroot[512];
    __shared__ float sbias[64];
    int t = threadIdx.x;
    for (int k = t; k < 512; k += 256) sroot[k] = root1[k];
    if (t < 64) sbias[t] = bias1[t];
    __syncthreads();

    int warp = t >> 5, lane = t & 31;
    int n = blockIdx.x * 8 + warp;
    float acc0 = sbias[lane], acc1 = sbias[lane + 32];
    const float* xr = x + n * 8;
#pragma unroll
    for (int i = 0; i < 8; i++) {
        float xv = __ldg(xr + i);
        acc0 = fmaf(xv, sroot[i * 64 + lane], acc0);
        acc1 = fmaf(xv, sroot[i * 64 + lane + 32], acc1);
    }
    g_h1[n * 64 + lane] = acc0;
    g_h1[n * 64 + lane + 32] = acc1;
}

// ---------------------------------------------------------------------------
// k_edge1: layer-1 edge messages (c_in=8 -> 4 i-pairs), packed f32x2,
// 8 edges/warp-iter, lane owns adjacent columns (2*lane, 2*lane+1),
// epilogue uses red.global.v2.f32.add (one REDG per edge per lane).
// edge_index is int32 (JAX x64 disabled).
// ---------------------------------------------------------------------------
#define EPB1 8
__global__ void __launch_bounds__(256, 2)
k_edge1(const float* __restrict__ x,
        const int* __restrict__ ei,
        const float* __restrict__ ea,
        const float* __restrict__ A1,
        const float* __restrict__ b1) {
    __shared__ float4 sWe[4 * 32];   // [p][l] {P(2p,c0),P(2p+1,c0),Q(2p,c0),Q(2p+1,c0)}, c0=2l
    __shared__ float4 sWo[4 * 32];   // same for c1=2l+1
    __shared__ float4 sB[4 * 32];    // {B(2p,c0),B(2p+1,c0),B(2p,c1),B(2p+1,c1)}
    __shared__ float  sx[8][EPB1 * 8];  // per warp: 8 edges x 8 feats

    int t = threadIdx.x;
    for (int k = t; k < 128; k += 256) {
        int p = k >> 5, o = k & 31;
        int i0 = 2 * p, c0 = 2 * o, c1 = 2 * o + 1;
        sWe[k] = make_float4(A1[i0 * 64 + c0],       A1[(i0 + 1) * 64 + c0],
                             A1[512 + i0 * 64 + c0], A1[512 + (i0 + 1) * 64 + c0]);
        sWo[k] = make_float4(A1[i0 * 64 + c1],       A1[(i0 + 1) * 64 + c1],
                             A1[512 + i0 * 64 + c1], A1[512 + (i0 + 1) * 64 + c1]);
        sB[k]  = make_float4(b1[i0 * 64 + c0], b1[(i0 + 1) * 64 + c0],
                             b1[i0 * 64 + c1], b1[(i0 + 1) * 64 + c1]);
    }
    __syncthreads();

    int warp = t >> 5, lane = t & 31;
    const unsigned long long* sx2 = (const unsigned long long*)sx[warp];
    const ulonglong2* pWe = (const ulonglong2*)sWe;
    const ulonglong2* pWo = (const ulonglong2*)sWo;
    const ulonglong2* pB  = (const ulonglong2*)sB;

    int gw = blockIdx.x * 8 + warp;
    int nwarps = gridDim.x * 8;
    const int* src = ei;
    const int* dst = ei + N_EDGES;

    for (int g = gw; g < N_EDGES / EPB1; g += nwarps) {
        int e0 = g * EPB1;
        int4 dA = *(const int4*)(dst + e0);
        int4 dB4 = *(const int4*)(dst + e0 + 4);
        {   // stage x rows: lane -> (edge = lane>>2, float2 j = lane&3)
            int e = lane >> 2, j = lane & 3;
            int s = src[e0 + e];
            float2 v = *(const float2*)(x + (size_t)s * 8 + j * 2);
            ((float2*)sx[warp])[e * 4 + j] = v;
        }
        unsigned long long a0d[EPB1], a1d[EPB1];
#pragma unroll
        for (int e = 0; e < EPB1; e++) {
            float2 at = *(const float2*)(ea + (size_t)(e0 + e) * 2);
            a0d[e] = pack2(at.x, at.x);
            a1d[e] = pack2(at.y, at.y);
        }
        __syncwarp();

        unsigned long long accE[EPB1], accO[EPB1];
#pragma unroll
        for (int e = 0; e < EPB1; e++) { accE[e] = 0ull; accO[e] = 0ull; }
#pragma unroll
        for (int p = 0; p < 4; p++) {
            ulonglong2 we = pWe[p * 32 + lane];
            ulonglong2 wo = pWo[p * 32 + lane];
            ulonglong2 bb = pB[p * 32 + lane];
#pragma unroll
            for (int e = 0; e < EPB1; e++) {
                unsigned long long h2 = sx2[e * 4 + p];
                unsigned long long wl = ffma2(a0d[e], we.x, bb.x);
                wl = relu2(ffma2(a1d[e], we.y, wl));
                accE[e] = ffma2(h2, wl, accE[e]);
                unsigned long long wh = ffma2(a0d[e], wo.x, bb.y);
                wh = relu2(ffma2(a1d[e], wo.y, wh));
                accO[e] = ffma2(h2, wh, accO[e]);
            }
        }
        int dd[EPB1] = {dA.x, dA.y, dA.z, dA.w, dB4.x, dB4.y, dB4.z, dB4.w};
#pragma unroll
        for (int e = 0; e < EPB1; e++) {
            float2 ae = unpack2(accE[e]);
            float2 ao = unpack2(accO[e]);
            red_v2(&g_h1[(size_t)dd[e] * 64 + 2 * lane], ae.x + ae.y, ao.x + ao.y);
        }
        __syncwarp();
    }
}

// ---------------------------------------------------------------------------
// k_init2: out[n,:] = h1[n,:64] @ root2[64,64] + bias2. 4 nodes per warp.
// ---------------------------------------------------------------------------
__global__ void k_init2(const float* __restrict__ root2,
                        const float* __restrict__ bias2,
                        float* __restrict__ out) {
    __shared__ float2 sR[64 * 32];
    __shared__ float  sb[64];
    int t = threadIdx.x;
    for (int k = t; k < 2048; k += 256) {
        int i = k >> 5, o = k & 31;
        sR[k] = make_float2(root2[i * 64 + o], root2[i * 64 + o + 32]);
    }
    if (t < 64) sb[t] = bias2[t];
    __syncthreads();

    int warp = t >> 5, lane = t & 31;
    int n0 = (blockIdx.x * 8 + warp) * 4;
    float hlo[4], hhi[4], acc0[4], acc1[4];
#pragma unroll
    for (int n = 0; n < 4; n++) {
        hlo[n] = g_h1[(n0 + n) * 64 + lane];
        hhi[n] = g_h1[(n0 + n) * 64 + lane + 32];
        acc0[n] = sb[lane];
        acc1[n] = sb[lane + 32];
    }
#pragma unroll
    for (int i = 0; i < 64; i++) {
        float2 r = sR[i * 32 + lane];
#pragma unroll
        for (int n = 0; n < 4; n++) {
            float hv = __shfl_sync(0xffffffffu, (i < 32) ? hlo[n] : hhi[n], i & 31);
            acc0[n] = fmaf(hv, r.x, acc0[n]);
            acc1[n] = fmaf(hv, r.y, acc1[n]);
        }
    }
#pragma unroll
    for (int n = 0; n < 4; n++) {
        out[(n0 + n) * 64 + lane]      = acc0[n];
        out[(n0 + n) * 64 + lane + 32] = acc1[n];
    }
}

// ---------------------------------------------------------------------------
// k_edge2: hot kernel (R4 core + dst prefetch + v2 reductions).
// Packed-over-i f32x2, 8 edges/warp-iter, warp-independent groups; lane owns
// adjacent output columns (2*lane, 2*lane+1) so the epilogue is ONE
// red.global.v2.f32.add per edge per lane (half the REDG instructions).
//   msg[e,o] = sum_i h1[src[e],i] * relu(a0*P[i,o] + a1*Q[i,o] + B[i,o])
// smem: sWe 16K | sWo 16K | sB 16K | staging 16K = 65536 B.
// ---------------------------------------------------------------------------
#define EPB2 8
__global__ void __launch_bounds__(256, 2)
k_edge2(const int* __restrict__ ei,
        const float* __restrict__ ea,
        const float* __restrict__ A2,
        const float* __restrict__ b2,
        float* __restrict__ out) {
    extern __shared__ float smem[];
    float4* sWe = (float4*)smem;                        // [32p][32l] col c0=2l
    float4* sWo = (float4*)(smem + 4096);               // col c1=2l+1
    float4* sB  = (float4*)(smem + 8192);               // {B c0 pair, B c1 pair}
    float*  sh  = smem + 12288;                         // 8 warps * 8 edges * 64

    int t = threadIdx.x;
    for (int k = t; k < 1024; k += 256) {
        int p = k >> 5, o = k & 31;
        int i0 = 2 * p, c0 = 2 * o, c1 = 2 * o + 1;
        sWe[k] = make_float4(A2[i0 * 64 + c0],        A2[(i0 + 1) * 64 + c0],
                             A2[4096 + i0 * 64 + c0], A2[4096 + (i0 + 1) * 64 + c0]);
        sWo[k] = make_float4(A2[i0 * 64 + c1],        A2[(i0 + 1) * 64 + c1],
                             A2[4096 + i0 * 64 + c1], A2[4096 + (i0 + 1) * 64 + c1]);
        sB[k]  = make_float4(b2[i0 * 64 + c0], b2[(i0 + 1) * 64 + c0],
                             b2[i0 * 64 + c1], b2[(i0 + 1) * 64 + c1]);
    }
    __syncthreads();

    int warp = t >> 5, lane = t & 31;
    float* shw = sh + warp * (EPB2 * 64);
    const unsigned long long* shw2 = (const unsigned long long*)shw;
    const ulonglong2* pWe = (const ulonglong2*)sWe;
    const ulonglong2* pWo = (const ulonglong2*)sWo;
    const ulonglong2* pB  = (const ulonglong2*)sB;

    int gw = blockIdx.x * 8 + warp;
    int nwarps = gridDim.x * 8;
    const int* src = ei;
    const int* dst = ei + N_EDGES;

    for (int g = gw; g < N_EDGES / EPB2; g += nwarps) {
        int e0 = g * EPB2;
        // prefetch dst indices early (hidden behind the 32-p compute below)
        int4 dA = *(const int4*)(dst + e0);
        int4 dB4 = *(const int4*)(dst + e0 + 4);
        unsigned long long a0d[EPB2], a1d[EPB2];
#pragma unroll
        for (int e = 0; e < EPB2; e++) {
            int s = src[e0 + e];
            // gather h1 row (256B coalesced) into smem, pairs over i
            float2 hv = *(const float2*)(&g_h1[s * 64 + lane * 2]);
            ((float2*)shw)[e * 32 + lane] = hv;
            float2 at = *(const float2*)(ea + (size_t)(e0 + e) * 2);
            a0d[e] = pack2(at.x, at.x);
            a1d[e] = pack2(at.y, at.y);
        }
        __syncwarp();

        unsigned long long accE[EPB2], accO[EPB2];
#pragma unroll
        for (int e = 0; e < EPB2; e++) { accE[e] = 0ull; accO[e] = 0ull; }
#pragma unroll 4
        for (int p = 0; p < 32; p++) {
            ulonglong2 we = pWe[p * 32 + lane];   // .x = {P0,P1}, .y = {Q0,Q1} (col c0)
            ulonglong2 wo = pWo[p * 32 + lane];   // same, col c1
            ulonglong2 bb = pB[p * 32 + lane];    // .x={B c0 pair} .y={B c1 pair}
#pragma unroll
            for (int e = 0; e < EPB2; e++) {
                unsigned long long h2 = shw2[e * 32 + p];   // broadcast
                unsigned long long wl = ffma2(a0d[e], we.x, bb.x);
                wl = relu2(ffma2(a1d[e], we.y, wl));
                accE[e] = ffma2(h2, wl, accE[e]);
                unsigned long long wh = ffma2(a0d[e], wo.x, bb.y);
                wh = relu2(ffma2(a1d[e], wo.y, wh));
                accO[e] = ffma2(h2, wh, accO[e]);
            }
        }
        int dd[EPB2] = {dA.x, dA.y, dA.z, dA.w, dB4.x, dB4.y, dB4.z, dB4.w};
#pragma unroll
        for (int e = 0; e < EPB2; e++) {
            float2 ae = unpack2(accE[e]);
            float2 ao = unpack2(accO[e]);
            red_v2(&out[(size_t)dd[e] * 64 + 2 * lane], ae.x + ae.y, ao.x + ao.y);
        }
        __syncwarp();
    }
}

// ---------------------------------------------------------------------------
// Launch: init1 -> edge1 -> init2 -> edge2 (default stream, graph-capturable).
// Inputs (metadata order):
//   0 x[16384,8] f32 | 1 edge_index[2,65536] i32 | 2 edge_attr[65536,2] f32
//   3 A1[2,512] | 4 b1[512] | 5 A2[2,4096] | 6 b2[4096]
//   7 root1[8,64] | 8 bias1[64] | 9 root2[64,64] | 10 bias2[64]
// ---------------------------------------------------------------------------
extern "C" void kernel_launch(void* const* d_in, const int* in_sizes, int n_in,
                              void* d_out, int out_size) {
    const float* x     = (const float*)d_in[0];
    const int*   ei    = (const int*)d_in[1];
    const float* ea    = (const float*)d_in[2];
    const float* A1    = (const float*)d_in[3];
    const float* b1    = (const float*)d_in[4];
    const float* A2    = (const float*)d_in[5];
    const float* b2    = (const float*)d_in[6];
    const float* root1 = (const float*)d_in[7];
    const float* bias1 = (const float*)d_in[8];
    const float* root2 = (const float*)d_in[9];
    const float* bias2 = (const float*)d_in[10];
    float* out = (float*)d_out;

    const int smem2 = 65536;
    cudaFuncSetAttribute(k_edge2, cudaFuncAttributeMaxDynamicSharedMemorySize, smem2);

    k_init1<<<N_NODES / 8, 256>>>(x, root1, bias1);
    k_edge1<<<296, 256>>>(x, ei, ea, A1, b1);
    k_init2<<<N_NODES / 32, 256>>>(root2, bias2, out);
    k_edge2<<<296, 256, smem2>>>(ei, ea, A2, b2, out);
}